// round 15
// baseline (speedup 1.0000x reference)
#include <cuda_runtime.h>
#include <cuda_fp16.h>
#include <cstdint>

#define VN 10000
#define RN 5
#define AN 8
#define CN 64
#define TN 64
#define KN 2560        /* R*A*C */
#define NNW 512        /* A*T   */
#define RA 40          /* R*A = K-chunks */

#define MT 64
#define NT 128
#define KC 64                     /* k-halfs per chunk: 128B rows = one (r,a) */
#define NITER (KN / KC)           /* 40 */
#define A_HALF_BYTES (MT * KC * 2)   /* 8192  */
#define B_HALF_BYTES (NT * KC * 2)   /* 16384 */
#define STAGE_BYTES (2 * A_HALF_BYTES + 2 * B_HALF_BYTES)  /* 49152 */

#define NTHREADS 384              /* 8 consumer warps + 4 producer warps */

// Scratch (device globals: no allocations allowed)
__device__ __half g_B1h[NNW * KN];         // BT1 hi  [n][k] (2.6 MB)
__device__ __half g_B1l[NNW * KN];
__device__ __half g_B2h[NNW * KN];
__device__ __half g_B2l[NNW * KN];
__device__ float  g_S [(size_t)VN * NNW];  // GEMM output, pre-pool (20.5 MB)
__device__ float  g_Y1[VN * CN];           // stage-1 output (2.56 MB)

// ---------------------------------------------------------------------------
// helpers
// ---------------------------------------------------------------------------
__device__ __forceinline__ uint32_t smem_u32(const void* p) {
    uint32_t a;
    asm("{ .reg .u64 t; cvta.to.shared.u64 t, %1; cvt.u32.u64 %0, t; }"
        : "=r"(a) : "l"(p));
    return a;
}
__device__ __forceinline__ void cpa16(uint32_t dst, const void* src) {
    asm volatile("cp.async.ca.shared.global [%0], [%1], 16;\n" :: "r"(dst), "l"(src));
}
__device__ __forceinline__ void cp_commit() {
    asm volatile("cp.async.commit_group;\n" ::);
}
template<int N> __device__ __forceinline__ void cp_wait() {
    asm volatile("cp.async.wait_group %0;\n" :: "n"(N));
}
__device__ __forceinline__ void ldsm4(uint32_t* r, uint32_t addr) {
    asm volatile("ldmatrix.sync.aligned.m8n8.x4.shared.b16 {%0,%1,%2,%3}, [%4];"
                 : "=r"(r[0]), "=r"(r[1]), "=r"(r[2]), "=r"(r[3]) : "r"(addr));
}
__device__ __forceinline__ void hmma(float* d, const uint32_t* a, const uint32_t* b) {
    asm volatile(
        "mma.sync.aligned.m16n8k16.row.col.f32.f16.f16.f32 "
        "{%0,%1,%2,%3}, {%4,%5,%6,%7}, {%8,%9}, {%0,%1,%2,%3};\n"
        : "+f"(d[0]), "+f"(d[1]), "+f"(d[2]), "+f"(d[3])
        : "r"(a[0]), "r"(a[1]), "r"(a[2]), "r"(a[3]), "r"(b[0]), "r"(b[1]));
}
// swizzled offset within a tile: rows of 128B (8 x 16B chunks)
__device__ __forceinline__ uint32_t swz(int row, int c) {
    return (uint32_t)(row * 128 + ((c ^ (row & 7)) << 4));
}
__device__ __forceinline__ void sts8(uint32_t addr, uint32_t a, uint32_t b) {
    asm volatile("st.shared.v2.b32 [%0], {%1, %2};" :: "r"(addr), "r"(a), "r"(b));
}

// ---------------------------------------------------------------------------
// Build BT[n=(o,t)][k=(r,a,c)] = T[t, r, (o+a)%A, c], fp16 hi/lo split.
// ---------------------------------------------------------------------------
__global__ void prep_rot_kernel(const float* __restrict__ T1,
                                const float* __restrict__ T2) {
    int i = blockIdx.x * blockDim.x + threadIdx.x;
    const int total = NNW * KN;
    const float* Tm; __half *Bh, *Bl; int e;
    if (i < total) { Tm = T1; Bh = g_B1h; Bl = g_B1l; e = i; }
    else           { Tm = T2; Bh = g_B2h; Bl = g_B2l; e = i - total; }
    int n = e / KN, k = e - n * KN;
    int c = k & 63; int ra = k >> 6; int a = ra & 7; int r = ra >> 3;
    int t = n & 63; int o = n >> 6;
    float v = Tm[((t * RN + r) * AN + ((o + a) & 7)) * CN + c];
    __half h = __float2half_rn(v);
    Bh[e] = h;
    Bl[e] = __float2half_rn(v - __half2float(h));
}

// ---------------------------------------------------------------------------
// Warp-specialized fused GEMM.
//   S[v][n] = (sum_i w_i * src[idx_i])[k] * BT[n][k]^T
// Warps 0-7: consumers (HMMA on chunk it).  Warps 8-11: producers (B cp.async
// + fused interp gather/blend/split/STS for chunk it+1) running CONCURRENTLY
// with the consumers, one __syncthreads per iteration. Double-buffered smem.
// ---------------------------------------------------------------------------
__global__ void __launch_bounds__(NTHREADS, 2)
gemm_fused_ws_kernel(const float* __restrict__ src,
                     const int*   __restrict__ bc_idx,
                     const float* __restrict__ bc_w,
                     const __half* __restrict__ Bh_g,
                     const __half* __restrict__ Bl_g) {
    extern __shared__ char dsm[];
    const uint32_t sb = smem_u32(dsm);
    // per stage: [Ah 8K][Al 8K][Bh 16K][Bl 16K]

    const int tid  = threadIdx.x;
    const int warp = tid >> 5, lane = tid & 31;
    const int n0 = blockIdx.x * NT;
    const int m0 = blockIdx.y * MT;
    const bool consumer = (warp < 8);

    // ---------------- producer: fill stage buf with chunk ck
    auto produce = [&](int ck) {
        const int ptid = tid - 256;              // 0..127
        const int buf = ck & 1;
        const uint32_t st = sb + buf * STAGE_BYTES;
        const int k0 = ck * KC;
        // B: 1024 segs x (hi,lo) -> 8 j-iters, 2 cpa each
        #pragma unroll
        for (int j = 0; j < 8; j++) {
            int id = ptid + j * 128;
            int row = id >> 3, c = id & 7;
            size_t gs = (size_t)(n0 + row) * KN + k0 + c * 8;
            uint32_t d = swz(row, c);
            cpa16(st + 2 * A_HALF_BYTES + d,                Bh_g + gs);
            cpa16(st + 2 * A_HALF_BYTES + B_HALF_BYTES + d, Bl_g + gs);
        }
        cp_commit();
        // A: 64 rows x 16 quads = 1024 tasks -> 8 per producer thread.
        // Stage 1: batch all idx/w loads (high MLP).
        int i0[8], i1[8], i2[8];
        float w0[8], w1[8], w2[8];
        #pragma unroll
        for (int j = 0; j < 8; j++) {
            int id = ptid + j * 128;
            int row = id >> 4;
            int v = m0 + row; if (v >= VN) v = VN - 1;
            int g = (v * RA + ck) * 3;
            i0[j] = __ldg(bc_idx + g);     i1[j] = __ldg(bc_idx + g + 1);
            i2[j] = __ldg(bc_idx + g + 2);
            w0[j] = __ldg(bc_w + g);       w1[j] = __ldg(bc_w + g + 1);
            w2[j] = __ldg(bc_w + g + 2);
        }
        // Stage 2: two waves of 4 tasks (bounded register pressure).
        #pragma unroll
        for (int wv = 0; wv < 2; wv++) {
            float4 x0[4], x1[4], x2[4];
            #pragma unroll
            for (int u = 0; u < 4; u++) {
                int j = wv * 4 + u;
                int id = ptid + j * 128;
                int q = id & 15;
                x0[u] = ((const float4*)(src + (size_t)i0[j] * CN))[q];
                x1[u] = ((const float4*)(src + (size_t)i1[j] * CN))[q];
                x2[u] = ((const float4*)(src + (size_t)i2[j] * CN))[q];
            }
            #pragma unroll
            for (int u = 0; u < 4; u++) {
                int j = wv * 4 + u;
                int id = ptid + j * 128;
                int row = id >> 4, q = id & 15;
                float rx = w0[j]*x0[u].x + w1[j]*x1[u].x + w2[j]*x2[u].x;
                float ry = w0[j]*x0[u].y + w1[j]*x1[u].y + w2[j]*x2[u].y;
                float rz = w0[j]*x0[u].z + w1[j]*x1[u].z + w2[j]*x2[u].z;
                float rw = w0[j]*x0[u].w + w1[j]*x1[u].w + w2[j]*x2[u].w;
                __half hx = __float2half_rn(rx), hy = __float2half_rn(ry);
                __half hz = __float2half_rn(rz), hw = __float2half_rn(rw);
                __half lx = __float2half_rn(rx - __half2float(hx));
                __half ly = __float2half_rn(ry - __half2float(hy));
                __half lz = __float2half_rn(rz - __half2float(hz));
                __half lw = __float2half_rn(rw - __half2float(hw));
                __half2 h01 = __halves2half2(hx, hy), h23 = __halves2half2(hz, hw);
                __half2 l01 = __halves2half2(lx, ly), l23 = __halves2half2(lz, lw);
                uint32_t d = swz(row, q >> 1) + (q & 1) * 8;
                sts8(st + d,                *(uint32_t*)&h01, *(uint32_t*)&h23);
                sts8(st + A_HALF_BYTES + d, *(uint32_t*)&l01, *(uint32_t*)&l23);
            }
        }
        cp_wait<0>();          // B for this chunk landed (producer-side)
    };

    float acc[2][4][4];
    if (consumer) {
        #pragma unroll
        for (int mi = 0; mi < 2; mi++)
            #pragma unroll
            for (int ni = 0; ni < 4; ni++)
                #pragma unroll
                for (int j = 0; j < 4; j++) acc[mi][ni][j] = 0.f;
    } else {
        produce(0);
    }
    __syncthreads();

    const int wm = warp >> 2, wn = warp & 3;     // consumer 2 x 4 warp grid

    for (int it = 0; it < NITER; it++) {
        const int buf = it & 1;
        if (consumer) {
            const uint32_t st  = sb + buf * STAGE_BYTES;
            const uint32_t sAh = st;
            const uint32_t sAl = st + A_HALF_BYTES;
            const uint32_t sBh = st + 2 * A_HALF_BYTES;
            const uint32_t sBl = st + 2 * A_HALF_BYTES + B_HALF_BYTES;
            #pragma unroll
            for (int ks = 0; ks < 4; ks++) {       // 4 k16-steps per chunk
                uint32_t ah[2][4], al[2][4];
                #pragma unroll
                for (int mi = 0; mi < 2; mi++) {
                    int row = wm * 32 + mi * 16 + (lane & 15);
                    int c   = ks * 2 + (lane >> 4);
                    ldsm4(ah[mi], sAh + swz(row, c));
                    ldsm4(al[mi], sAl + swz(row, c));
                }
                #pragma unroll
                for (int nj = 0; nj < 2; nj++) {
                    uint32_t bh[4], bl[4];
                    int row = wn * 32 + nj * 16 + ((lane >> 4) << 3) + (lane & 7);
                    int c   = ks * 2 + ((lane >> 3) & 1);
                    ldsm4(bh, sBh + swz(row, c));
                    ldsm4(bl, sBl + swz(row, c));
                    #pragma unroll
                    for (int mi = 0; mi < 2; mi++) {
                        hmma(acc[mi][2*nj],   ah[mi], &bh[0]);
                        hmma(acc[mi][2*nj],   al[mi], &bh[0]);
                        hmma(acc[mi][2*nj],   ah[mi], &bl[0]);
                        hmma(acc[mi][2*nj+1], ah[mi], &bh[2]);
                        hmma(acc[mi][2*nj+1], al[mi], &bh[2]);
                        hmma(acc[mi][2*nj+1], ah[mi], &bl[2]);
                    }
                }
            }
        } else {
            if (it + 1 < NITER) produce(it + 1);
        }
        __syncthreads();
    }

    // ---------------- epilogue: consumers store raw S
    if (consumer) {
        const int gr = lane >> 2, gc = (lane & 3) * 2;
        #pragma unroll
        for (int mi = 0; mi < 2; mi++) {
            int v = m0 + wm * 32 + mi * 16 + gr;
            #pragma unroll
            for (int ni = 0; ni < 4; ni++) {
                int n = n0 + wn * 32 + ni * 8 + gc;
                if (v < VN)
                    *(float2*)&g_S[(size_t)v * NNW + n] =
                        make_float2(acc[mi][ni][0], acc[mi][ni][1]);
                if (v + 8 < VN)
                    *(float2*)&g_S[(size_t)(v + 8) * NNW + n] =
                        make_float2(acc[mi][ni][2], acc[mi][ni][3]);
            }
        }
    }
}

// ---------------------------------------------------------------------------
// pool: bias -> norm argmax over o -> BN -> (resid) -> relu. 1 block per v.
// ---------------------------------------------------------------------------
template<bool STAGE2>
__global__ void pool_kernel(const float* __restrict__ bias,
                            const float* __restrict__ gamma,
                            const float* __restrict__ beta,
                            const float* __restrict__ resid,
                            float* __restrict__ out) {
    const int v = blockIdx.x, t = threadIdx.x;
    __shared__ float ssum[2][8];
    const float* Sv = g_S + (size_t)v * NNW;
    const float b = bias[t];
    float val[8], q[8];
    #pragma unroll
    for (int o = 0; o < 8; o++) {
        val[o] = Sv[o * 64 + t] + b;
        q[o] = val[o] * val[o];
    }
    #pragma unroll
    for (int sft = 1; sft < 32; sft <<= 1)
        #pragma unroll
        for (int o = 0; o < 8; o++)
            q[o] += __shfl_xor_sync(0xffffffffu, q[o], sft);
    if ((t & 31) == 0) {
        #pragma unroll
        for (int o = 0; o < 8; o++) ssum[t >> 5][o] = q[o];
    }
    __syncthreads();
    float best = ssum[0][0] + ssum[1][0];
    int bo = 0;
    #pragma unroll
    for (int o = 1; o < 8; o++) {
        float s = ssum[0][o] + ssum[1][o];
        if (s > best) { best = s; bo = o; }   // first max wins
    }
    const float INV = 0.999500373802f;        // rsqrt(1 + 1e-3)
    float y = gamma[t] * (val[bo] * INV) + beta[t];
    if (STAGE2) y += resid[v * 64 + t];
    y = fmaxf(y, 0.f);
    out[v * 64 + t] = y;
}

// ---------------------------------------------------------------------------
extern "C" void kernel_launch(void* const* d_in, const int* in_sizes, int n_in,
                              void* d_out, int out_size) {
    const float* signal = (const float*)d_in[0];
    const float* bc_w   = (const float*)d_in[1];
    const float* t1     = (const float*)d_in[2];
    const float* bias1  = (const float*)d_in[3];
    const float* gamma1 = (const float*)d_in[4];
    const float* beta1  = (const float*)d_in[5];
    const float* t2     = (const float*)d_in[6];
    const float* bias2  = (const float*)d_in[7];
    const float* gamma2 = (const float*)d_in[8];
    const float* beta2  = (const float*)d_in[9];
    const int*   bc_idx = (const int*)d_in[10];
    float* out = (float*)d_out;

    void *pB1h, *pB1l, *pB2h, *pB2l, *pY1;
    cudaGetSymbolAddress(&pB1h, g_B1h);
    cudaGetSymbolAddress(&pB1l, g_B1l);
    cudaGetSymbolAddress(&pB2h, g_B2h);
    cudaGetSymbolAddress(&pB2l, g_B2l);
    cudaGetSymbolAddress(&pY1,  g_Y1);

    const int smem_bytes = 2 * STAGE_BYTES;   // 98304
    cudaFuncSetAttribute(gemm_fused_ws_kernel,
                         cudaFuncAttributeMaxDynamicSharedMemorySize, smem_bytes);

    dim3 ggrid(NNW / NT, (VN + MT - 1) / MT);   // 4 x 157, n-tile fastest

    prep_rot_kernel<<<(2 * NNW * KN) / 256, 256>>>(t1, t2);
    gemm_fused_ws_kernel<<<ggrid, NTHREADS, smem_bytes>>>(
        signal, bc_idx, bc_w, (const __half*)pB1h, (const __half*)pB1l);
    pool_kernel<false><<<VN, 64>>>(bias1, gamma1, beta1, nullptr, (float*)pY1);
    gemm_fused_ws_kernel<<<ggrid, NTHREADS, smem_bytes>>>(
        (const float*)pY1, bc_idx, bc_w, (const __half*)pB2h, (const __half*)pB2l);
    pool_kernel<true><<<VN, 64>>>(bias2, gamma2, beta2, signal, out);
}

// round 17
// speedup vs baseline: 1.6902x; 1.6902x over previous
#include <cuda_runtime.h>
#include <cuda_fp16.h>
#include <cstdint>

#define VN 10000
#define RN 5
#define AN 8
#define CN 64
#define TN 64
#define KN 2560        /* R*A*C */
#define NNW 512        /* A*T   */

#define MT 64
#define NT 128
#define KC 64                     /* k-halfs per chunk: 128B rows */
#define NITER (KN / KC)           /* 40 */
#define KSPLIT 2
#define CPS (NITER / KSPLIT)      /* 20 chunks per split */
#define A_HALF_BYTES (MT * KC * 2)   /* 8192  */
#define B_HALF_BYTES (NT * KC * 2)   /* 16384 */
#define STAGE_BYTES (2 * A_HALF_BYTES + 2 * B_HALF_BYTES)  /* 49152 */

// Scratch (device globals: no allocations allowed)
__device__ __half g_Xh[(size_t)VN * KN];   // interp result, fp16-hi (51 MB)
__device__ __half g_Xl[(size_t)VN * KN];   // interp result, fp16-lo
__device__ __half g_B1h[NNW * KN];         // BT1 hi  [n][k] (2.6 MB)
__device__ __half g_B1l[NNW * KN];
__device__ __half g_B2h[NNW * KN];
__device__ __half g_B2l[NNW * KN];
__device__ float  g_S [KSPLIT][(size_t)VN * NNW];  // partial GEMM outputs
__device__ float  g_Y1[VN * CN];           // stage-1 output

// ---------------------------------------------------------------------------
// helpers
// ---------------------------------------------------------------------------
__device__ __forceinline__ uint32_t smem_u32(const void* p) {
    uint32_t a;
    asm("{ .reg .u64 t; cvta.to.shared.u64 t, %1; cvt.u32.u64 %0, t; }"
        : "=r"(a) : "l"(p));
    return a;
}
__device__ __forceinline__ void cpa16(uint32_t dst, const void* src) {
    asm volatile("cp.async.ca.shared.global [%0], [%1], 16;\n" :: "r"(dst), "l"(src));
}
__device__ __forceinline__ void cp_commit() {
    asm volatile("cp.async.commit_group;\n" ::);
}
template<int N> __device__ __forceinline__ void cp_wait() {
    asm volatile("cp.async.wait_group %0;\n" :: "n"(N));
}
__device__ __forceinline__ void ldsm4(uint32_t* r, uint32_t addr) {
    asm volatile("ldmatrix.sync.aligned.m8n8.x4.shared.b16 {%0,%1,%2,%3}, [%4];"
                 : "=r"(r[0]), "=r"(r[1]), "=r"(r[2]), "=r"(r[3]) : "r"(addr));
}
__device__ __forceinline__ void hmma(float* d, const uint32_t* a, const uint32_t* b) {
    asm volatile(
        "mma.sync.aligned.m16n8k16.row.col.f32.f16.f16.f32 "
        "{%0,%1,%2,%3}, {%4,%5,%6,%7}, {%8,%9}, {%0,%1,%2,%3};\n"
        : "+f"(d[0]), "+f"(d[1]), "+f"(d[2]), "+f"(d[3])
        : "r"(a[0]), "r"(a[1]), "r"(a[2]), "r"(a[3]), "r"(b[0]), "r"(b[1]));
}
// swizzled offset within a tile: rows of 128B (8 x 16B chunks)
__device__ __forceinline__ uint32_t swz(int row, int c) {
    return (uint32_t)(row * 128 + ((c ^ (row & 7)) << 4));
}

// ---------------------------------------------------------------------------
// Build BT[n=(o,t)][k=(r,a,c)] = T[t, r, (o+a)%A, c], fp16 hi/lo split.
// ---------------------------------------------------------------------------
__global__ void prep_rot_kernel(const float* __restrict__ T1,
                                const float* __restrict__ T2) {
    int i = blockIdx.x * blockDim.x + threadIdx.x;
    const int total = NNW * KN;
    const float* Tm; __half *Bh, *Bl; int e;
    if (i < total) { Tm = T1; Bh = g_B1h; Bl = g_B1l; e = i; }
    else           { Tm = T2; Bh = g_B2h; Bl = g_B2l; e = i - total; }
    int n = e / KN, k = e - n * KN;
    int c = k & 63; int ra = k >> 6; int a = ra & 7; int r = ra >> 3;
    int t = n & 63; int o = n >> 6;
    float v = Tm[((t * RN + r) * AN + ((o + a) & 7)) * CN + c];
    __half h = __float2half_rn(v);
    Bh[e] = h;
    Bl[e] = __float2half_rn(v - __half2float(h));
}

// ---------------------------------------------------------------------------
// interp: X[v,(r,a),c] = sum_i w_i * src[idx_i, c]; fp16 hi/lo split output.
// ---------------------------------------------------------------------------
__global__ void interp_kernel(const float* __restrict__ src_ext,
                              const int*   __restrict__ bc_idx,
                              const float* __restrict__ bc_w,
                              int use_y1) {
    const float* src = use_y1 ? (const float*)g_Y1 : src_ext;
    int i = blockIdx.x * blockDim.x + threadIdx.x;  // V*R*A*16 threads
    int q = i & 15;
    int g = i >> 4;
    int i0 = bc_idx[g*3+0], i1 = bc_idx[g*3+1], i2 = bc_idx[g*3+2];
    float w0 = bc_w[g*3+0],  w1 = bc_w[g*3+1],  w2 = bc_w[g*3+2];
    float4 x0 = ((const float4*)(src + (size_t)i0 * CN))[q];
    float4 x1 = ((const float4*)(src + (size_t)i1 * CN))[q];
    float4 x2 = ((const float4*)(src + (size_t)i2 * CN))[q];
    float4 r;
    r.x = w0*x0.x + w1*x1.x + w2*x2.x;
    r.y = w0*x0.y + w1*x1.y + w2*x2.y;
    r.z = w0*x0.z + w1*x1.z + w2*x2.z;
    r.w = w0*x0.w + w1*x1.w + w2*x2.w;
    __half hx = __float2half_rn(r.x), hy = __float2half_rn(r.y);
    __half hz = __float2half_rn(r.z), hw = __float2half_rn(r.w);
    __half lx = __float2half_rn(r.x - __half2float(hx));
    __half ly = __float2half_rn(r.y - __half2float(hy));
    __half lz = __float2half_rn(r.z - __half2float(hz));
    __half lw = __float2half_rn(r.w - __half2float(hw));
    __half2 h01 = __halves2half2(hx, hy), h23 = __halves2half2(hz, hw);
    __half2 l01 = __halves2half2(lx, ly), l23 = __halves2half2(lz, lw);
    size_t off = (size_t)g * 64 + q * 4;
    uint2 hv = make_uint2(*(uint32_t*)&h01, *(uint32_t*)&h23);
    uint2 lv = make_uint2(*(uint32_t*)&l01, *(uint32_t*)&l23);
    *(uint2*)&g_Xh[off] = hv;
    *(uint2*)&g_Xl[off] = lv;
}

// ---------------------------------------------------------------------------
// fp16x3 GEMM via mma.sync.m16n8k16: S[z][v][n] = partial over K-half z.
// CTA 64m x 128n x (K/2); 8 warps (2m x 4n), warp tile 32m x 32n.
// Split-K=2 halves tile duration -> wave quantization 71% -> 85% efficient.
// K chunks of 64 halfs; cp.async double-buffered; ldmatrix.x4 frags.
// ---------------------------------------------------------------------------
__global__ void __launch_bounds__(256, 2)
gemm_kernel(const __half* __restrict__ Bh_g, const __half* __restrict__ Bl_g) {
    extern __shared__ char dsm[];
    const uint32_t sb = smem_u32(dsm);
    // per stage: [Ah 8K][Al 8K][Bh 16K][Bl 16K]

    const int tid  = threadIdx.x;
    const int warp = tid >> 5, lane = tid & 31;
    const int wm = warp >> 2, wn = warp & 3;           // 2 x 4 warp grid
    const int n0 = blockIdx.x * NT;
    const int m0 = blockIdx.y * MT;
    const int z  = blockIdx.z;                         // K-split index
    const int c0 = z * CPS;                            // first chunk

    float acc[2][4][4];
    #pragma unroll
    for (int mi = 0; mi < 2; mi++)
        #pragma unroll
        for (int ni = 0; ni < 4; ni++)
            #pragma unroll
            for (int j = 0; j < 4; j++) acc[mi][ni][j] = 0.f;

    auto issue = [&](int it) {                         // it = local chunk idx
        const int buf = it & 1;
        const int k0  = (c0 + it) * KC;
        const uint32_t st = sb + buf * STAGE_BYTES;
        // A: 64 rows x 8 chunks = 512 segs -> 2 per thread (hi+lo each)
        #pragma unroll
        for (int j = 0; j < 2; j++) {
            int id = tid + j * 256;
            int row = id >> 3, c = id & 7;
            int v = m0 + row; if (v >= VN) v = VN - 1;
            size_t gs = (size_t)v * KN + k0 + c * 8;
            uint32_t d = swz(row, c);
            cpa16(st + d,                g_Xh + gs);
            cpa16(st + A_HALF_BYTES + d, g_Xl + gs);
        }
        // B: 128 rows x 8 chunks = 1024 segs -> 4 per thread (hi+lo each)
        #pragma unroll
        for (int j = 0; j < 4; j++) {
            int id = tid + j * 256;
            int row = id >> 3, c = id & 7;
            size_t gs = (size_t)(n0 + row) * KN + k0 + c * 8;
            uint32_t d = swz(row, c);
            cpa16(st + 2 * A_HALF_BYTES + d,                Bh_g + gs);
            cpa16(st + 2 * A_HALF_BYTES + B_HALF_BYTES + d, Bl_g + gs);
        }
        cp_commit();
    };

    issue(0);
    for (int it = 0; it < CPS; it++) {
        const int buf = it & 1;
        if (it + 1 < CPS) { issue(it + 1); cp_wait<1>(); }
        else              { cp_wait<0>(); }
        __syncthreads();
        const uint32_t st  = sb + buf * STAGE_BYTES;
        const uint32_t sAh = st;
        const uint32_t sAl = st + A_HALF_BYTES;
        const uint32_t sBh = st + 2 * A_HALF_BYTES;
        const uint32_t sBl = st + 2 * A_HALF_BYTES + B_HALF_BYTES;

        #pragma unroll
        for (int ks = 0; ks < 4; ks++) {           // 4 k16-steps per chunk
            // A fragments: rows m0..; lanes 0-15 pick m rows, lanes/16 pick k8
            uint32_t ah[2][4], al[2][4];
            #pragma unroll
            for (int mi = 0; mi < 2; mi++) {
                int row = wm * 32 + mi * 16 + (lane & 15);
                int c   = ks * 2 + (lane >> 4);
                ldsm4(ah[mi], sAh + swz(row, c));
                ldsm4(al[mi], sAl + swz(row, c));
            }
            // B fragment pairs: nj covers ni=2nj, 2nj+1
            uint32_t bh[2][4], bl[2][4];
            #pragma unroll
            for (int nj = 0; nj < 2; nj++) {
                int row = wn * 32 + nj * 16 + ((lane >> 4) << 3) + (lane & 7);
                int c   = ks * 2 + ((lane >> 3) & 1);
                ldsm4(bh[nj], sBh + swz(row, c));
                ldsm4(bl[nj], sBl + swz(row, c));
            }
            #pragma unroll
            for (int mi = 0; mi < 2; mi++)
                #pragma unroll
                for (int nj = 0; nj < 2; nj++) {
                    hmma(acc[mi][2*nj],   ah[mi], &bh[nj][0]);
                    hmma(acc[mi][2*nj],   al[mi], &bh[nj][0]);
                    hmma(acc[mi][2*nj],   ah[mi], &bl[nj][0]);
                    hmma(acc[mi][2*nj+1], ah[mi], &bh[nj][2]);
                    hmma(acc[mi][2*nj+1], al[mi], &bh[nj][2]);
                    hmma(acc[mi][2*nj+1], ah[mi], &bl[nj][2]);
                }
        }
        __syncthreads();
    }

    // store raw partial S for this K-split
    float* Sz = g_S[z];
    const int gr = lane >> 2, gc = (lane & 3) * 2;
    #pragma unroll
    for (int mi = 0; mi < 2; mi++) {
        int v = m0 + wm * 32 + mi * 16 + gr;
        #pragma unroll
        for (int ni = 0; ni < 4; ni++) {
            int n = n0 + wn * 32 + ni * 8 + gc;
            if (v < VN)
                *(float2*)&Sz[(size_t)v * NNW + n] =
                    make_float2(acc[mi][ni][0], acc[mi][ni][1]);
            if (v + 8 < VN)
                *(float2*)&Sz[(size_t)(v + 8) * NNW + n] =
                    make_float2(acc[mi][ni][2], acc[mi][ni][3]);
        }
    }
}

// ---------------------------------------------------------------------------
// pool: sum K-split partials + bias -> norm argmax over o -> BN -> (resid)
// -> relu. 1 block per v.
// ---------------------------------------------------------------------------
template<bool STAGE2>
__global__ void pool_kernel(const float* __restrict__ bias,
                            const float* __restrict__ gamma,
                            const float* __restrict__ beta,
                            const float* __restrict__ resid,
                            float* __restrict__ out) {
    const int v = blockIdx.x, t = threadIdx.x;
    __shared__ float ssum[2][8];
    const float* S0 = g_S[0] + (size_t)v * NNW;
    const float* S1 = g_S[1] + (size_t)v * NNW;
    const float b = bias[t];
    float val[8], q[8];
    #pragma unroll
    for (int o = 0; o < 8; o++) {
        val[o] = S0[o * 64 + t] + S1[o * 64 + t] + b;
        q[o] = val[o] * val[o];
    }
    #pragma unroll
    for (int sft = 1; sft < 32; sft <<= 1)
        #pragma unroll
        for (int o = 0; o < 8; o++)
            q[o] += __shfl_xor_sync(0xffffffffu, q[o], sft);
    if ((t & 31) == 0) {
        #pragma unroll
        for (int o = 0; o < 8; o++) ssum[t >> 5][o] = q[o];
    }
    __syncthreads();
    float best = ssum[0][0] + ssum[1][0];
    int bo = 0;
    #pragma unroll
    for (int o = 1; o < 8; o++) {
        float s = ssum[0][o] + ssum[1][o];
        if (s > best) { best = s; bo = o; }   // first max wins
    }
    const float INV = 0.999500373802f;        // rsqrt(1 + 1e-3)
    float y = gamma[t] * (val[bo] * INV) + beta[t];
    if (STAGE2) y += resid[v * 64 + t];
    y = fmaxf(y, 0.f);
    out[v * 64 + t] = y;
}

// ---------------------------------------------------------------------------
extern "C" void kernel_launch(void* const* d_in, const int* in_sizes, int n_in,
                              void* d_out, int out_size) {
    const float* signal = (const float*)d_in[0];
    const float* bc_w   = (const float*)d_in[1];
    const float* t1     = (const float*)d_in[2];
    const float* bias1  = (const float*)d_in[3];
    const float* gamma1 = (const float*)d_in[4];
    const float* beta1  = (const float*)d_in[5];
    const float* t2     = (const float*)d_in[6];
    const float* bias2  = (const float*)d_in[7];
    const float* gamma2 = (const float*)d_in[8];
    const float* beta2  = (const float*)d_in[9];
    const int*   bc_idx = (const int*)d_in[10];
    float* out = (float*)d_out;

    void *pB1h, *pB1l, *pB2h, *pB2l, *pY1;
    cudaGetSymbolAddress(&pB1h, g_B1h);
    cudaGetSymbolAddress(&pB1l, g_B1l);
    cudaGetSymbolAddress(&pB2h, g_B2h);
    cudaGetSymbolAddress(&pB2l, g_B2l);
    cudaGetSymbolAddress(&pY1,  g_Y1);

    const int smem_bytes = 2 * STAGE_BYTES;   // 98304
    cudaFuncSetAttribute(gemm_kernel,
                         cudaFuncAttributeMaxDynamicSharedMemorySize, smem_bytes);

    dim3 ggrid(NNW / NT, (VN + MT - 1) / MT, KSPLIT);   // 4 x 157 x 2

    prep_rot_kernel<<<(2 * NNW * KN) / 256, 256>>>(t1, t2);
    interp_kernel<<<(VN * RN * AN * 16) / 256, 256>>>(signal, bc_idx, bc_w, 0);
    gemm_kernel<<<ggrid, 256, smem_bytes>>>((const __half*)pB1h, (const __half*)pB1l);
    pool_kernel<false><<<VN, 64>>>(bias1, gamma1, beta1, nullptr, (float*)pY1);
    interp_kernel<<<(VN * RN * AN * 16) / 256, 256>>>(nullptr, bc_idx, bc_w, 1);
    gemm_kernel<<<ggrid, 256, smem_bytes>>>((const __half*)pB2h, (const __half*)pB2l);
    pool_kernel<true><<<VN, 64>>>(bias2, gamma2, beta2, signal, out);
}